// round 13
// baseline (speedup 1.0000x reference)
#include <cuda_runtime.h>
#include <cuda_fp16.h>

#define NN   100000
#define NE   1600000
#define F    128
#define MPAD 100096   // 782 * 128

// fp16 feature buffers: Xh, Hh, T1h, T2h (zero-init; padded rows stay 0)
__device__ __half g_hbuf[4ull * MPAD * F];
__device__ int    g_rowptr[NN + 1];
__device__ int    g_cnt[NN];          // invariant: zero at entry to kernel_launch
__device__ int2   g_edge[NE];         // {col, weight-bits}
// Folded Cheb weights, split fp16 hi/lo (exact), layout [n][384]
__device__ __half g_wh[4 * 128 * 384];
__device__ __half g_wl[4 * 128 * 384];

// ------------------------------------------------ prep: histogram + x->fp16 + weight fold
__device__ __forceinline__ void wmod_one(const float* __restrict__ W, int nout, int mat,
                                         int tid, int stride) {
    __half* oh = g_wh + mat * (128 * 384);
    __half* ol = g_wl + mat * (128 * 384);
    int tot = nout * 384;
    for (int idx = tid; idx < tot; idx += stride) {
        int n = idx / 384, k = idx - n * 384;
        float v;
        if (k < 128)      v = W[n * 384 + k] - W[n * 384 + 256 + k];
        else if (k < 256) v = W[n * 384 + k];
        else              v = 2.0f * W[n * 384 + k];
        __half h = __float2half_rn(v);
        __half l = __float2half_rn(v - __half2float(h));
        oh[idx] = h;
        ol[idx] = l;
    }
}

__global__ void k_prep(const int* __restrict__ row, const float4* __restrict__ x4,
                       __half2* __restrict__ Xh2, int n4,
                       const float* __restrict__ W0, const float* __restrict__ W1,
                       const float* __restrict__ W2, const float* __restrict__ W3) {
    int tid = blockIdx.x * blockDim.x + threadIdx.x;
    int stride = gridDim.x * blockDim.x;
    for (int e = tid; e < NE; e += stride) atomicAdd(&g_cnt[row[e]], 1);
    for (int i = tid; i < n4; i += stride) {
        float4 v = x4[i];
        Xh2[2 * i]     = __floats2half2_rn(v.x, v.y);
        Xh2[2 * i + 1] = __floats2half2_rn(v.z, v.w);
    }
    wmod_one(W0, 128, 0, tid, stride);
    wmod_one(W1, 128, 1, tid, stride);
    wmod_one(W2, 128, 2, tid, stride);
    wmod_one(W3, 64,  3, tid, stride);
}

__global__ void k_scan() {
    __shared__ int ss[1024];
    const int T = 1024, C = (NN + T - 1) / T;
    int t = threadIdx.x, base = t * C, s = 0;
    for (int i = 0; i < C; i++) { int idx = base + i; if (idx < NN) s += g_cnt[idx]; }
    ss[t] = s;
    __syncthreads();
    for (int off = 1; off < T; off <<= 1) {
        int v = (t >= off) ? ss[t - off] : 0;
        __syncthreads();
        ss[t] += v;
        __syncthreads();
    }
    int run = ss[t] - s;
    for (int i = 0; i < C; i++) {
        int idx = base + i;
        if (idx < NN) {
            int c = g_cnt[idx];
            g_rowptr[idx] = run;
            g_cnt[idx]    = run;
            run += c;
        }
    }
    if (t == T - 1) g_rowptr[NN] = run;
}

__global__ void k_scatter(const int* __restrict__ row, const int* __restrict__ col,
                          const float* __restrict__ w) {
    for (int e = blockIdx.x * blockDim.x + threadIdx.x; e < NE; e += gridDim.x * blockDim.x) {
        int r = row[e];
        int p = atomicAdd(&g_cnt[r], 1);
        g_edge[p] = make_int2(col[e], __float_as_int(w[e]));
    }
}

// ------------------------------------------------ SpMM: warp per node (no divergence),
// lane owns 4 features (uint2 = 2 half2), fp32 accumulate, fp16 out.
__device__ __forceinline__ void acc4(float2* a, float w, const uint2& r) {
    float2 f;
    f = __half22float2(*reinterpret_cast<const __half2*>(&r.x));
    a[0].x = fmaf(w, f.x, a[0].x); a[0].y = fmaf(w, f.y, a[0].y);
    f = __half22float2(*reinterpret_cast<const __half2*>(&r.y));
    a[1].x = fmaf(w, f.x, a[1].x); a[1].y = fmaf(w, f.y, a[1].y);
}

__global__ void k_spmm(const uint2* __restrict__ src, uint2* __restrict__ dsth) {
    int node = (blockIdx.x * blockDim.x + threadIdx.x) >> 5;   // grid exact: no guard
    int lane = threadIdx.x & 31;
    int s = __ldg(&g_rowptr[node]), e = __ldg(&g_rowptr[node + 1]);
    float2 a[2] = {{0.f,0.f},{0.f,0.f}};
    float2 b[2] = {{0.f,0.f},{0.f,0.f}};
    int i = s;
    for (; i + 2 <= e; i += 2) {
        int2 m0 = __ldg(&g_edge[i]);
        int2 m1 = __ldg(&g_edge[i + 1]);
        uint2 r0 = __ldg(&src[m0.x * 32 + lane]);
        uint2 r1 = __ldg(&src[m1.x * 32 + lane]);
        acc4(a, __int_as_float(m0.y), r0);
        acc4(b, __int_as_float(m1.y), r1);
    }
    if (i < e) {
        int2 m = __ldg(&g_edge[i]);
        uint2 r = __ldg(&src[m.x * 32 + lane]);
        acc4(a, __int_as_float(m.y), r);
    }
    uint2 o;
    __half2 h0 = __floats2half2_rn(a[0].x + b[0].x, a[0].y + b[0].y);
    __half2 h1 = __floats2half2_rn(a[1].x + b[1].x, a[1].y + b[1].y);
    o.x = *reinterpret_cast<unsigned*>(&h0);
    o.y = *reinterpret_cast<unsigned*>(&h1);
    dsth[node * 32 + lane] = o;
}

// ------------------------------------------------ fp16 tensor-core GEMM (R12 config)
__device__ __forceinline__ void mma_f16(float* c, const unsigned* a, const unsigned* b) {
    asm volatile(
        "mma.sync.aligned.m16n8k16.row.col.f32.f16.f16.f32 "
        "{%0,%1,%2,%3}, {%4,%5,%6,%7}, {%8,%9}, {%0,%1,%2,%3};"
        : "+f"(c[0]), "+f"(c[1]), "+f"(c[2]), "+f"(c[3])
        : "r"(a[0]), "r"(a[1]), "r"(a[2]), "r"(a[3]), "r"(b[0]), "r"(b[1]));
}

__device__ __forceinline__ void ldsm_x4(unsigned* r, unsigned addr) {
    asm volatile("ldmatrix.sync.aligned.m8n8.x4.shared.b16 {%0,%1,%2,%3}, [%4];"
                 : "=r"(r[0]), "=r"(r[1]), "=r"(r[2]), "=r"(r[3]) : "r"(addr));
}

__device__ __forceinline__ void ldsm_x2(unsigned* r, unsigned addr) {
    asm volatile("ldmatrix.sync.aligned.m8n8.x2.shared.b16 {%0,%1}, [%2];"
                 : "=r"(r[0]), "=r"(r[1]) : "r"(addr));
}

template <int NOUT, bool RELU, bool RES, bool OUTF32, bool OUTH, bool LOPASS>
__global__ void __launch_bounds__(256)
k_gemm(const __half* __restrict__ A0, const __half* __restrict__ A1, const __half* __restrict__ A2,
       const __half* __restrict__ BH, const __half* __restrict__ BL,
       const float* __restrict__ bias, const __half* __restrict__ res,
       float* __restrict__ out, __half2* __restrict__ outh) {
    constexpr int BM = 128;
    constexpr int WC  = NOUT / 32;
    constexpr int WR  = 8 / WC;
    constexpr int MT  = BM / (WR * 16);
    constexpr int NT  = 4;
    constexpr int LDA = 40;
    constexpr int NB  = NOUT * 4 / 256;
    constexpr int NSEL = LOPASS ? 2 : 1;

    __shared__ __half As[BM][LDA];
    __shared__ __half Bs[NSEL][NOUT][LDA];

    int t = threadIdx.x, lane = t & 31, w = t >> 5;
    int g = lane >> 2, tq = lane & 3;
    int wm = (w / WC) * (MT * 16);
    int wn = (w % WC) * 32;
    int m0 = blockIdx.x * BM;

    unsigned asBase = (unsigned)__cvta_generic_to_shared(&As[0][0]);
    unsigned bsBase = (unsigned)__cvta_generic_to_shared(&Bs[0][0][0]);

    float acc[MT][NT][4];
#pragma unroll
    for (int i = 0; i < MT; i++)
#pragma unroll
        for (int j = 0; j < NT; j++)
#pragma unroll
            for (int q = 0; q < 4; q++) acc[i][j][q] = 0.f;

    int aRow = lane & 15, aCol = (lane >> 4) << 3;
    int bN = lane & 7, bQ = lane >> 3;
    int bSel = LOPASS ? (bQ >> 1) : 0;
    int bCol = (bQ & 1) << 3;
    int aR0 = t >> 2, aC0 = (t & 3) * 8;

    uint4 pa[2];
    {
        const __half* A = A0;
#pragma unroll
        for (int i = 0; i < 2; i++)
            pa[i] = *reinterpret_cast<const uint4*>(&A[(m0 + aR0 + i * 64) * F + aC0]);
    }

#pragma unroll 1
    for (int kti = 0; kti < 12; kti++) {
        int kt = kti * 32;
#pragma unroll
        for (int i = 0; i < 2; i++)
            *reinterpret_cast<uint4*>(&As[aR0 + i * 64][aC0]) = pa[i];
#pragma unroll
        for (int i = 0; i < NB; i++) {
            int idx = t + i * 256;
            int r = idx >> 2, c8 = (idx & 3) * 8;
            *reinterpret_cast<uint4*>(&Bs[0][r][c8]) =
                *reinterpret_cast<const uint4*>(&BH[r * 384 + kt + c8]);
            if (LOPASS)
                *reinterpret_cast<uint4*>(&Bs[NSEL - 1][r][c8]) =
                    *reinterpret_cast<const uint4*>(&BL[r * 384 + kt + c8]);
        }
        __syncthreads();
        if (kti < 11) {
            int ktn = kt + 32;
            const __half* A = (ktn < 128) ? A0 : ((ktn < 256) ? A1 : A2);
            int kc = ktn & 127;
#pragma unroll
            for (int i = 0; i < 2; i++)
                pa[i] = *reinterpret_cast<const uint4*>(&A[(m0 + aR0 + i * 64) * F + kc + aC0]);
        }
#pragma unroll
        for (int ks = 0; ks < 2; ks++) {
            int kb = ks * 16;
            unsigned a[MT][4];
#pragma unroll
            for (int mt = 0; mt < MT; mt++)
                ldsm_x4(a[mt], asBase + ((wm + mt * 16 + aRow) * LDA + kb + aCol) * 2);
            if (LOPASS) {
                unsigned bb[NT][4];
#pragma unroll
                for (int nt = 0; nt < NT; nt++)
                    ldsm_x4(bb[nt], bsBase + ((bSel * NOUT + wn + nt * 8 + bN) * LDA + kb + bCol) * 2);
#pragma unroll
                for (int mt = 0; mt < MT; mt++)
#pragma unroll
                    for (int nt = 0; nt < NT; nt++) {
                        mma_f16(acc[mt][nt], a[mt], bb[nt]);
                        mma_f16(acc[mt][nt], a[mt], bb[nt] + 2);
                    }
            } else {
                unsigned bb[NT][2];
#pragma unroll
                for (int nt = 0; nt < NT; nt++)
                    ldsm_x2(bb[nt], bsBase + (((wn + nt * 8 + (lane & 7)) * LDA + kb + ((lane >> 3) << 3)) * 2));
#pragma unroll
                for (int mt = 0; mt < MT; mt++)
#pragma unroll
                    for (int nt = 0; nt < NT; nt++)
                        mma_f16(acc[mt][nt], a[mt], bb[nt]);
            }
        }
        __syncthreads();
    }

#pragma unroll
    for (int mt = 0; mt < MT; mt++)
#pragma unroll
        for (int nt = 0; nt < NT; nt++) {
            int n = wn + nt * 8 + tq * 2;
            float b0 = __ldg(&bias[n]), b1 = __ldg(&bias[n + 1]);
#pragma unroll
            for (int half = 0; half < 2; half++) {
                int m = m0 + wm + mt * 16 + g + half * 8;
                if (m >= NN) continue;
                float v0 = acc[mt][nt][2 * half]     + b0;
                float v1 = acc[mt][nt][2 * half + 1] + b1;
                if (RES) {
                    float2 rf = __half22float2(*reinterpret_cast<const __half2*>(&res[m * F + n]));
                    v0 += rf.x; v1 += rf.y;
                }
                if (RELU) { v0 = fmaxf(v0, 0.f); v1 = fmaxf(v1, 0.f); }
                if (OUTF32)
                    *reinterpret_cast<float2*>(&out[m * NOUT + n]) = make_float2(v0, v1);
                if (OUTH)
                    outh[m * (NOUT / 2) + n / 2] = __floats2half2_rn(v0, v1);
            }
        }
}

// ------------------------------------------------ launch
extern "C" void kernel_launch(void* const* d_in, const int* in_sizes, int n_in,
                              void* d_out, int out_size) {
    const float* x     = (const float*)d_in[0];
    const int*   ei    = (const int*)d_in[1];
    const float* ew    = (const float*)d_in[2];
    const float* W_in  = (const float*)d_in[3];
    const float* b_in  = (const float*)d_in[4];
    const float* W_h1  = (const float*)d_in[5];
    const float* b_h1  = (const float*)d_in[6];
    const float* W_h2  = (const float*)d_in[7];
    const float* b_h2  = (const float*)d_in[8];
    const float* W_out = (const float*)d_in[9];
    const float* b_out = (const float*)d_in[10];
    float* out = (float*)d_out;

    const int* row = ei;
    const int* col = ei + NE;

    __half* hbuf; cudaGetSymbolAddress((void**)&hbuf, g_hbuf);
    int* cnt;     cudaGetSymbolAddress((void**)&cnt,  g_cnt);
    __half* wh;   cudaGetSymbolAddress((void**)&wh,   g_wh);
    __half* wl;   cudaGetSymbolAddress((void**)&wl,   g_wl);

    const size_t S = (size_t)MPAD * F;
    __half* Xh  = hbuf;
    __half* Hh  = hbuf + S;
    __half* T1h = hbuf + 2 * S;
    __half* T2h = hbuf + 3 * S;
    const int WSZ = 128 * 384;
    __half *WH0 = wh,           *WL0 = wl;
    __half *WH1 = wh + WSZ,     *WL1 = wl + WSZ;
    __half *WH2 = wh + 2 * WSZ, *WL2 = wl + 2 * WSZ;
    __half *WH3 = wh + 3 * WSZ, *WL3 = wl + 3 * WSZ;

    const int spmmGrid = (NN * 32) / 256;   // 12500, exact
    const int gemmGrid = MPAD / 128;        // 782

    k_prep<<<2048, 256>>>(row, (const float4*)x, (__half2*)Xh, NN * F / 4,
                          W_in, W_h1, W_h2, W_out);
    k_scan<<<1, 1024>>>();
    k_scatter<<<1024, 256>>>(row, col, ew);

    // layer 1
    k_spmm<<<spmmGrid, 256>>>((const uint2*)Xh,  (uint2*)T1h);
    k_spmm<<<spmmGrid, 256>>>((const uint2*)T1h, (uint2*)T2h);
    k_gemm<128, true, false, false, true, false><<<gemmGrid, 256>>>(
        Xh, T1h, T2h, WH0, WL0, b_in, nullptr, nullptr, (__half2*)Hh);

    // layer 2 (residual Hh): Hh -> Xh
    k_spmm<<<spmmGrid, 256>>>((const uint2*)Hh,  (uint2*)T1h);
    k_spmm<<<spmmGrid, 256>>>((const uint2*)T1h, (uint2*)T2h);
    k_gemm<128, true, true, false, true, false><<<gemmGrid, 256>>>(
        Hh, T1h, T2h, WH1, WL1, b_h1, Hh, nullptr, (__half2*)Xh);

    // layer 3 (residual Xh): Xh -> Hh
    k_spmm<<<spmmGrid, 256>>>((const uint2*)Xh,  (uint2*)T1h);
    k_spmm<<<spmmGrid, 256>>>((const uint2*)T1h, (uint2*)T2h);
    k_gemm<128, true, true, false, true, false><<<gemmGrid, 256>>>(
        Xh, T1h, T2h, WH2, WL2, b_h2, Xh, nullptr, (__half2*)Hh);

    // output layer: Hh -> out (N x 64, fp32), 2-pass weights for final precision
    k_spmm<<<spmmGrid, 256>>>((const uint2*)Hh,  (uint2*)T1h);
    k_spmm<<<spmmGrid, 256>>>((const uint2*)T1h, (uint2*)T2h);
    k_gemm<64, false, false, true, false, true><<<gemmGrid, 256>>>(
        Hh, T1h, T2h, WH3, WL3, b_out, nullptr, out, nullptr);

    // restore g_cnt=0 invariant for the next call
    cudaMemsetAsync(cnt, 0, NN * sizeof(int));
}

// round 14
// speedup vs baseline: 1.0355x; 1.0355x over previous
#include <cuda_runtime.h>
#include <cuda_fp16.h>

#define NN   100000
#define NE   1600000
#define F    128
#define MPAD 100096   // 782 * 128

// fp16 feature buffers: Xh, Hh, T1h, T2h (zero-init; padded rows stay 0)
__device__ __half g_hbuf[4ull * MPAD * F];
__device__ int    g_rowptr[NN + 1];
__device__ int    g_cnt[NN];          // invariant: zero at entry to kernel_launch
__device__ int2   g_edge[NE];         // {col, weight-bits}; pairs at even idx are 16B-aligned
// Folded Cheb weights, split fp16 hi/lo (exact), layout [n][384]
__device__ __half g_wh[4 * 128 * 384];
__device__ __half g_wl[4 * 128 * 384];

// ------------------------------------------------ prep: histogram + x->fp16 + weight fold
__device__ __forceinline__ void wmod_one(const float* __restrict__ W, int nout, int mat,
                                         int tid, int stride) {
    __half* oh = g_wh + mat * (128 * 384);
    __half* ol = g_wl + mat * (128 * 384);
    int tot = nout * 384;
    for (int idx = tid; idx < tot; idx += stride) {
        int n = idx / 384, k = idx - n * 384;
        float v;
        if (k < 128)      v = W[n * 384 + k] - W[n * 384 + 256 + k];
        else if (k < 256) v = W[n * 384 + k];
        else              v = 2.0f * W[n * 384 + k];
        __half h = __float2half_rn(v);
        __half l = __float2half_rn(v - __half2float(h));
        oh[idx] = h;
        ol[idx] = l;
    }
}

__global__ void k_prep(const int* __restrict__ row, const float4* __restrict__ x4,
                       __half2* __restrict__ Xh2, int n4,
                       const float* __restrict__ W0, const float* __restrict__ W1,
                       const float* __restrict__ W2, const float* __restrict__ W3) {
    int tid = blockIdx.x * blockDim.x + threadIdx.x;
    int stride = gridDim.x * blockDim.x;
    for (int e = tid; e < NE; e += stride) atomicAdd(&g_cnt[row[e]], 1);
    for (int i = tid; i < n4; i += stride) {
        float4 v = x4[i];
        Xh2[2 * i]     = __floats2half2_rn(v.x, v.y);
        Xh2[2 * i + 1] = __floats2half2_rn(v.z, v.w);
    }
    wmod_one(W0, 128, 0, tid, stride);
    wmod_one(W1, 128, 1, tid, stride);
    wmod_one(W2, 128, 2, tid, stride);
    wmod_one(W3, 64,  3, tid, stride);
}

__global__ void k_scan() {
    __shared__ int ss[1024];
    const int T = 1024, C = (NN + T - 1) / T;
    int t = threadIdx.x, base = t * C, s = 0;
    for (int i = 0; i < C; i++) { int idx = base + i; if (idx < NN) s += g_cnt[idx]; }
    ss[t] = s;
    __syncthreads();
    for (int off = 1; off < T; off <<= 1) {
        int v = (t >= off) ? ss[t - off] : 0;
        __syncthreads();
        ss[t] += v;
        __syncthreads();
    }
    int run = ss[t] - s;
    for (int i = 0; i < C; i++) {
        int idx = base + i;
        if (idx < NN) {
            int c = g_cnt[idx];
            g_rowptr[idx] = run;
            g_cnt[idx]    = run;
            run += c;
        }
    }
    if (t == T - 1) g_rowptr[NN] = run;
}

__global__ void k_scatter(const int* __restrict__ row, const int* __restrict__ col,
                          const float* __restrict__ w) {
    for (int e = blockIdx.x * blockDim.x + threadIdx.x; e < NE; e += gridDim.x * blockDim.x) {
        int r = row[e];
        int p = atomicAdd(&g_cnt[r], 1);
        g_edge[p] = make_int2(col[e], __float_as_int(w[e]));
    }
}

// ------------------------------------------------ SpMM (R12 shape + paired meta LDG.128)
__device__ __forceinline__ void acc8(float2* a, float w, const uint4& r) {
    float2 f;
    f = __half22float2(*reinterpret_cast<const __half2*>(&r.x));
    a[0].x = fmaf(w, f.x, a[0].x); a[0].y = fmaf(w, f.y, a[0].y);
    f = __half22float2(*reinterpret_cast<const __half2*>(&r.y));
    a[1].x = fmaf(w, f.x, a[1].x); a[1].y = fmaf(w, f.y, a[1].y);
    f = __half22float2(*reinterpret_cast<const __half2*>(&r.z));
    a[2].x = fmaf(w, f.x, a[2].x); a[2].y = fmaf(w, f.y, a[2].y);
    f = __half22float2(*reinterpret_cast<const __half2*>(&r.w));
    a[3].x = fmaf(w, f.x, a[3].x); a[3].y = fmaf(w, f.y, a[3].y);
}

__global__ void k_spmm(const uint4* __restrict__ src, uint4* __restrict__ dsth) {
    int hw = (blockIdx.x * blockDim.x + threadIdx.x) >> 4;
    int lane = threadIdx.x & 15;
    int s = __ldg(&g_rowptr[hw]), e = __ldg(&g_rowptr[hw + 1]);
    float2 a[4] = {{0.f,0.f},{0.f,0.f},{0.f,0.f},{0.f,0.f}};
    float2 b[4] = {{0.f,0.f},{0.f,0.f},{0.f,0.f},{0.f,0.f}};
    int i = s;
    // peel one edge if start is odd -> remaining pairs are 16B-aligned
    if ((i & 1) && i < e) {
        int2 m = __ldg(&g_edge[i]);
        uint4 r = __ldg(&src[m.x * 16 + lane]);
        acc8(a, __int_as_float(m.y), r);
        i++;
    }
    for (; i + 2 <= e; i += 2) {
        int4 mm = __ldg(reinterpret_cast<const int4*>(&g_edge[i]));  // 2 edges, 1 LDG.128
        uint4 r0 = __ldg(&src[mm.x * 16 + lane]);
        uint4 r1 = __ldg(&src[mm.z * 16 + lane]);
        acc8(a, __int_as_float(mm.y), r0);
        acc8(b, __int_as_float(mm.w), r1);
    }
    if (i < e) {
        int2 m = __ldg(&g_edge[i]);
        uint4 r = __ldg(&src[m.x * 16 + lane]);
        acc8(a, __int_as_float(m.y), r);
    }
    uint4 o;
    unsigned* op = reinterpret_cast<unsigned*>(&o);
#pragma unroll
    for (int q = 0; q < 4; q++) {
        __half2 hv = __floats2half2_rn(a[q].x + b[q].x, a[q].y + b[q].y);
        op[q] = *reinterpret_cast<unsigned*>(&hv);
    }
    dsth[hw * 16 + lane] = o;
}

// ------------------------------------------------ fp16 tensor-core GEMM (R12 config)
__device__ __forceinline__ void mma_f16(float* c, const unsigned* a, const unsigned* b) {
    asm volatile(
        "mma.sync.aligned.m16n8k16.row.col.f32.f16.f16.f32 "
        "{%0,%1,%2,%3}, {%4,%5,%6,%7}, {%8,%9}, {%0,%1,%2,%3};"
        : "+f"(c[0]), "+f"(c[1]), "+f"(c[2]), "+f"(c[3])
        : "r"(a[0]), "r"(a[1]), "r"(a[2]), "r"(a[3]), "r"(b[0]), "r"(b[1]));
}

__device__ __forceinline__ void ldsm_x4(unsigned* r, unsigned addr) {
    asm volatile("ldmatrix.sync.aligned.m8n8.x4.shared.b16 {%0,%1,%2,%3}, [%4];"
                 : "=r"(r[0]), "=r"(r[1]), "=r"(r[2]), "=r"(r[3]) : "r"(addr));
}

__device__ __forceinline__ void ldsm_x2(unsigned* r, unsigned addr) {
    asm volatile("ldmatrix.sync.aligned.m8n8.x2.shared.b16 {%0,%1}, [%2];"
                 : "=r"(r[0]), "=r"(r[1]) : "r"(addr));
}

template <int NOUT, bool RELU, bool RES, bool OUTF32, bool OUTH, bool LOPASS>
__global__ void __launch_bounds__(256)
k_gemm(const __half* __restrict__ A0, const __half* __restrict__ A1, const __half* __restrict__ A2,
       const __half* __restrict__ BH, const __half* __restrict__ BL,
       const float* __restrict__ bias, const __half* __restrict__ res,
       float* __restrict__ out, __half2* __restrict__ outh) {
    constexpr int BM = 128;
    constexpr int WC  = NOUT / 32;
    constexpr int WR  = 8 / WC;
    constexpr int MT  = BM / (WR * 16);
    constexpr int NT  = 4;
    constexpr int LDA = 40;
    constexpr int NB  = NOUT * 4 / 256;
    constexpr int NSEL = LOPASS ? 2 : 1;

    __shared__ __half As[BM][LDA];
    __shared__ __half Bs[NSEL][NOUT][LDA];

    int t = threadIdx.x, lane = t & 31, w = t >> 5;
    int g = lane >> 2, tq = lane & 3;
    int wm = (w / WC) * (MT * 16);
    int wn = (w % WC) * 32;
    int m0 = blockIdx.x * BM;

    unsigned asBase = (unsigned)__cvta_generic_to_shared(&As[0][0]);
    unsigned bsBase = (unsigned)__cvta_generic_to_shared(&Bs[0][0][0]);

    float acc[MT][NT][4];
#pragma unroll
    for (int i = 0; i < MT; i++)
#pragma unroll
        for (int j = 0; j < NT; j++)
#pragma unroll
            for (int q = 0; q < 4; q++) acc[i][j][q] = 0.f;

    int aRow = lane & 15, aCol = (lane >> 4) << 3;
    int bN = lane & 7, bQ = lane >> 3;
    int bSel = LOPASS ? (bQ >> 1) : 0;
    int bCol = (bQ & 1) << 3;
    int aR0 = t >> 2, aC0 = (t & 3) * 8;

    uint4 pa[2];
    {
        const __half* A = A0;
#pragma unroll
        for (int i = 0; i < 2; i++)
            pa[i] = *reinterpret_cast<const uint4*>(&A[(m0 + aR0 + i * 64) * F + aC0]);
    }

#pragma unroll 1
    for (int kti = 0; kti < 12; kti++) {
        int kt = kti * 32;
#pragma unroll
        for (int i = 0; i < 2; i++)
            *reinterpret_cast<uint4*>(&As[aR0 + i * 64][aC0]) = pa[i];
#pragma unroll
        for (int i = 0; i < NB; i++) {
            int idx = t + i * 256;
            int r = idx >> 2, c8 = (idx & 3) * 8;
            *reinterpret_cast<uint4*>(&Bs[0][r][c8]) =
                *reinterpret_cast<const uint4*>(&BH[r * 384 + kt + c8]);
            if (LOPASS)
                *reinterpret_cast<uint4*>(&Bs[NSEL - 1][r][c8]) =
                    *reinterpret_cast<const uint4*>(&BL[r * 384 + kt + c8]);
        }
        __syncthreads();
        if (kti < 11) {
            int ktn = kt + 32;
            const __half* A = (ktn < 128) ? A0 : ((ktn < 256) ? A1 : A2);
            int kc = ktn & 127;
#pragma unroll
            for (int i = 0; i < 2; i++)
                pa[i] = *reinterpret_cast<const uint4*>(&A[(m0 + aR0 + i * 64) * F + kc + aC0]);
        }
#pragma unroll
        for (int ks = 0; ks < 2; ks++) {
            int kb = ks * 16;
            unsigned a[MT][4];
#pragma unroll
            for (int mt = 0; mt < MT; mt++)
                ldsm_x4(a[mt], asBase + ((wm + mt * 16 + aRow) * LDA + kb + aCol) * 2);
            if (LOPASS) {
                unsigned bb[NT][4];
#pragma unroll
                for (int nt = 0; nt < NT; nt++)
                    ldsm_x4(bb[nt], bsBase + ((bSel * NOUT + wn + nt * 8 + bN) * LDA + kb + bCol) * 2);
#pragma unroll
                for (int mt = 0; mt < MT; mt++)
#pragma unroll
                    for (int nt = 0; nt < NT; nt++) {
                        mma_f16(acc[mt][nt], a[mt], bb[nt]);
                        mma_f16(acc[mt][nt], a[mt], bb[nt] + 2);
                    }
            } else {
                unsigned bb[NT][2];
#pragma unroll
                for (int nt = 0; nt < NT; nt++)
                    ldsm_x2(bb[nt], bsBase + (((wn + nt * 8 + (lane & 7)) * LDA + kb + ((lane >> 3) << 3)) * 2));
#pragma unroll
                for (int mt = 0; mt < MT; mt++)
#pragma unroll
                    for (int nt = 0; nt < NT; nt++)
                        mma_f16(acc[mt][nt], a[mt], bb[nt]);
            }
        }
        __syncthreads();
    }

#pragma unroll
    for (int mt = 0; mt < MT; mt++)
#pragma unroll
        for (int nt = 0; nt < NT; nt++) {
            int n = wn + nt * 8 + tq * 2;
            float b0 = __ldg(&bias[n]), b1 = __ldg(&bias[n + 1]);
#pragma unroll
            for (int half = 0; half < 2; half++) {
                int m = m0 + wm + mt * 16 + g + half * 8;
                if (m >= NN) continue;
                float v0 = acc[mt][nt][2 * half]     + b0;
                float v1 = acc[mt][nt][2 * half + 1] + b1;
                if (RES) {
                    float2 rf = __half22float2(*reinterpret_cast<const __half2*>(&res[m * F + n]));
                    v0 += rf.x; v1 += rf.y;
                }
                if (RELU) { v0 = fmaxf(v0, 0.f); v1 = fmaxf(v1, 0.f); }
                if (OUTF32)
                    *reinterpret_cast<float2*>(&out[m * NOUT + n]) = make_float2(v0, v1);
                if (OUTH)
                    outh[m * (NOUT / 2) + n / 2] = __floats2half2_rn(v0, v1);
            }
        }
}

// ------------------------------------------------ launch
extern "C" void kernel_launch(void* const* d_in, const int* in_sizes, int n_in,
                              void* d_out, int out_size) {
    const float* x     = (const float*)d_in[0];
    const int*   ei    = (const int*)d_in[1];
    const float* ew    = (const float*)d_in[2];
    const float* W_in  = (const float*)d_in[3];
    const float* b_in  = (const float*)d_in[4];
    const float* W_h1  = (const float*)d_in[5];
    const float* b_h1  = (const float*)d_in[6];
    const float* W_h2  = (const float*)d_in[7];
    const float* b_h2  = (const float*)d_in[8];
    const float* W_out = (const float*)d_in[9];
    const float* b_out = (const float*)d_in[10];
    float* out = (float*)d_out;

    const int* row = ei;
    const int* col = ei + NE;

    __half* hbuf; cudaGetSymbolAddress((void**)&hbuf, g_hbuf);
    int* cnt;     cudaGetSymbolAddress((void**)&cnt,  g_cnt);
    __half* wh;   cudaGetSymbolAddress((void**)&wh,   g_wh);
    __half* wl;   cudaGetSymbolAddress((void**)&wl,   g_wl);

    const size_t S = (size_t)MPAD * F;
    __half* Xh  = hbuf;
    __half* Hh  = hbuf + S;
    __half* T1h = hbuf + 2 * S;
    __half* T2h = hbuf + 3 * S;
    const int WSZ = 128 * 384;
    __half *WH0 = wh,           *WL0 = wl;
    __half *WH1 = wh + WSZ,     *WL1 = wl + WSZ;
    __half *WH2 = wh + 2 * WSZ, *WL2 = wl + 2 * WSZ;
    __half *WH3 = wh + 3 * WSZ, *WL3 = wl + 3 * WSZ;

    const int spmmGrid = (NN * 16) / 256;   // 6250, exact
    const int gemmGrid = MPAD / 128;        // 782

    k_prep<<<2048, 256>>>(row, (const float4*)x, (__half2*)Xh, NN * F / 4,
                          W_in, W_h1, W_h2, W_out);
    k_scan<<<1, 1024>>>();
    k_scatter<<<1024, 256>>>(row, col, ew);

    // layer 1
    k_spmm<<<spmmGrid, 256>>>((const uint4*)Xh,  (uint4*)T1h);
    k_spmm<<<spmmGrid, 256>>>((const uint4*)T1h, (uint4*)T2h);
    k_gemm<128, true, false, false, true, false><<<gemmGrid, 256>>>(
        Xh, T1h, T2h, WH0, WL0, b_in, nullptr, nullptr, (__half2*)Hh);

    // layer 2 (residual Hh): Hh -> Xh
    k_spmm<<<spmmGrid, 256>>>((const uint4*)Hh,  (uint4*)T1h);
    k_spmm<<<spmmGrid, 256>>>((const uint4*)T1h, (uint4*)T2h);
    k_gemm<128, true, true, false, true, false><<<gemmGrid, 256>>>(
        Hh, T1h, T2h, WH1, WL1, b_h1, Hh, nullptr, (__half2*)Xh);

    // layer 3 (residual Xh): Xh -> Hh
    k_spmm<<<spmmGrid, 256>>>((const uint4*)Xh,  (uint4*)T1h);
    k_spmm<<<spmmGrid, 256>>>((const uint4*)T1h, (uint4*)T2h);
    k_gemm<128, true, true, false, true, false><<<gemmGrid, 256>>>(
        Xh, T1h, T2h, WH2, WL2, b_h2, Xh, nullptr, (__half2*)Hh);

    // output layer: Hh -> out (N x 64, fp32), 2-pass weights for final precision
    k_spmm<<<spmmGrid, 256>>>((const uint4*)Hh,  (uint4*)T1h);
    k_spmm<<<spmmGrid, 256>>>((const uint4*)T1h, (uint4*)T2h);
    k_gemm<64, false, false, true, false, true><<<gemmGrid, 256>>>(
        Hh, T1h, T2h, WH3, WL3, b_out, nullptr, out, nullptr);

    // restore g_cnt=0 invariant for the next call
    cudaMemsetAsync(cnt, 0, NN * sizeof(int));
}

// round 15
// speedup vs baseline: 1.1342x; 1.0953x over previous
#include <cuda_runtime.h>
#include <cuda_fp16.h>

#define NN   100000
#define NE   1600000
#define F    128
#define MPAD 100096   // 782 * 128

// fp16 feature buffers: Xh, Hh, T1h, T2h (zero-init; padded rows stay 0)
__device__ __half g_hbuf[4ull * MPAD * F];
__device__ int    g_rowptr[NN + 1];
__device__ int    g_cnt[NN];          // invariant: zero at entry to kernel_launch
__device__ int2   g_edge[NE];         // {col, weight-bits}
// Folded Cheb weights, split fp16 hi/lo (exact), layout [n][384]
__device__ __half g_wh[4 * 128 * 384];
__device__ __half g_wl[4 * 128 * 384];

// ------------------------------------------------ prep: histogram + x->fp16 + weight fold
__device__ __forceinline__ void wmod_one(const float* __restrict__ W, int nout, int mat,
                                         int tid, int stride) {
    __half* oh = g_wh + mat * (128 * 384);
    __half* ol = g_wl + mat * (128 * 384);
    int tot = nout * 384;
    for (int idx = tid; idx < tot; idx += stride) {
        int n = idx / 384, k = idx - n * 384;
        float v;
        if (k < 128)      v = W[n * 384 + k] - W[n * 384 + 256 + k];
        else if (k < 256) v = W[n * 384 + k];
        else              v = 2.0f * W[n * 384 + k];
        __half h = __float2half_rn(v);
        __half l = __float2half_rn(v - __half2float(h));
        oh[idx] = h;
        ol[idx] = l;
    }
}

__global__ void k_prep(const int* __restrict__ row, const float4* __restrict__ x4,
                       __half2* __restrict__ Xh2, int n4,
                       const float* __restrict__ W0, const float* __restrict__ W1,
                       const float* __restrict__ W2, const float* __restrict__ W3) {
    int tid = blockIdx.x * blockDim.x + threadIdx.x;
    int stride = gridDim.x * blockDim.x;
    for (int e = tid; e < NE; e += stride) atomicAdd(&g_cnt[row[e]], 1);
    for (int i = tid; i < n4; i += stride) {
        float4 v = x4[i];
        Xh2[2 * i]     = __floats2half2_rn(v.x, v.y);
        Xh2[2 * i + 1] = __floats2half2_rn(v.z, v.w);
    }
    wmod_one(W0, 128, 0, tid, stride);
    wmod_one(W1, 128, 1, tid, stride);
    wmod_one(W2, 128, 2, tid, stride);
    wmod_one(W3, 64,  3, tid, stride);
}

__global__ void k_scan() {
    __shared__ int ss[1024];
    const int T = 1024, C = (NN + T - 1) / T;
    int t = threadIdx.x, base = t * C, s = 0;
    for (int i = 0; i < C; i++) { int idx = base + i; if (idx < NN) s += g_cnt[idx]; }
    ss[t] = s;
    __syncthreads();
    for (int off = 1; off < T; off <<= 1) {
        int v = (t >= off) ? ss[t - off] : 0;
        __syncthreads();
        ss[t] += v;
        __syncthreads();
    }
    int run = ss[t] - s;
    for (int i = 0; i < C; i++) {
        int idx = base + i;
        if (idx < NN) {
            int c = g_cnt[idx];
            g_rowptr[idx] = run;
            g_cnt[idx]    = run;
            run += c;
        }
    }
    if (t == T - 1) g_rowptr[NN] = run;
}

__global__ void k_scatter(const int* __restrict__ row, const int* __restrict__ col,
                          const float* __restrict__ w) {
    for (int e = blockIdx.x * blockDim.x + threadIdx.x; e < NE; e += gridDim.x * blockDim.x) {
        int r = row[e];
        int p = atomicAdd(&g_cnt[r], 1);
        g_edge[p] = make_int2(col[e], __float_as_int(w[e]));
    }
}

// ------------------------------------------------ SpMM (exact R12 config: best measured)
__device__ __forceinline__ void acc8(float2* a, float w, const uint4& r) {
    float2 f;
    f = __half22float2(*reinterpret_cast<const __half2*>(&r.x));
    a[0].x = fmaf(w, f.x, a[0].x); a[0].y = fmaf(w, f.y, a[0].y);
    f = __half22float2(*reinterpret_cast<const __half2*>(&r.y));
    a[1].x = fmaf(w, f.x, a[1].x); a[1].y = fmaf(w, f.y, a[1].y);
    f = __half22float2(*reinterpret_cast<const __half2*>(&r.z));
    a[2].x = fmaf(w, f.x, a[2].x); a[2].y = fmaf(w, f.y, a[2].y);
    f = __half22float2(*reinterpret_cast<const __half2*>(&r.w));
    a[3].x = fmaf(w, f.x, a[3].x); a[3].y = fmaf(w, f.y, a[3].y);
}

__global__ void k_spmm(const uint4* __restrict__ src, uint4* __restrict__ dsth) {
    int hw = (blockIdx.x * blockDim.x + threadIdx.x) >> 4;
    int lane = threadIdx.x & 15;
    int s = __ldg(&g_rowptr[hw]), e = __ldg(&g_rowptr[hw + 1]);
    float2 a[4] = {{0.f,0.f},{0.f,0.f},{0.f,0.f},{0.f,0.f}};
    float2 b[4] = {{0.f,0.f},{0.f,0.f},{0.f,0.f},{0.f,0.f}};
    int i = s;
    for (; i + 2 <= e; i += 2) {
        int2 m0 = __ldg(&g_edge[i]);
        int2 m1 = __ldg(&g_edge[i + 1]);
        uint4 r0 = __ldg(&src[m0.x * 16 + lane]);
        uint4 r1 = __ldg(&src[m1.x * 16 + lane]);
        acc8(a, __int_as_float(m0.y), r0);
        acc8(b, __int_as_float(m1.y), r1);
    }
    if (i < e) {
        int2 m = __ldg(&g_edge[i]);
        uint4 r = __ldg(&src[m.x * 16 + lane]);
        acc8(a, __int_as_float(m.y), r);
    }
    uint4 o;
    unsigned* op = reinterpret_cast<unsigned*>(&o);
#pragma unroll
    for (int q = 0; q < 4; q++) {
        __half2 hv = __floats2half2_rn(a[q].x + b[q].x, a[q].y + b[q].y);
        op[q] = *reinterpret_cast<unsigned*>(&hv);
    }
    dsth[hw * 16 + lane] = o;
}

// ------------------------------------------------ fp16 tensor-core GEMM
// Double-buffered smem, A+B register prefetch, ONE sync per k-tile.
__device__ __forceinline__ void mma_f16(float* c, const unsigned* a, const unsigned* b) {
    asm volatile(
        "mma.sync.aligned.m16n8k16.row.col.f32.f16.f16.f32 "
        "{%0,%1,%2,%3}, {%4,%5,%6,%7}, {%8,%9}, {%0,%1,%2,%3};"
        : "+f"(c[0]), "+f"(c[1]), "+f"(c[2]), "+f"(c[3])
        : "r"(a[0]), "r"(a[1]), "r"(a[2]), "r"(a[3]), "r"(b[0]), "r"(b[1]));
}

__device__ __forceinline__ void ldsm_x4(unsigned* r, unsigned addr) {
    asm volatile("ldmatrix.sync.aligned.m8n8.x4.shared.b16 {%0,%1,%2,%3}, [%4];"
                 : "=r"(r[0]), "=r"(r[1]), "=r"(r[2]), "=r"(r[3]) : "r"(addr));
}

__device__ __forceinline__ void ldsm_x2(unsigned* r, unsigned addr) {
    asm volatile("ldmatrix.sync.aligned.m8n8.x2.shared.b16 {%0,%1}, [%2];"
                 : "=r"(r[0]), "=r"(r[1]) : "r"(addr));
}

template <int NOUT, bool RELU, bool RES, bool OUTF32, bool OUTH, bool LOPASS>
__global__ void __launch_bounds__(256, 2)
k_gemm(const __half* __restrict__ A0, const __half* __restrict__ A1, const __half* __restrict__ A2,
       const __half* __restrict__ BH, const __half* __restrict__ BL,
       const float* __restrict__ bias, const __half* __restrict__ res,
       float* __restrict__ out, __half2* __restrict__ outh) {
    constexpr int BM = 128;
    constexpr int WC  = NOUT / 32;
    constexpr int WR  = 8 / WC;
    constexpr int MT  = BM / (WR * 16);
    constexpr int NT  = 4;
    constexpr int LDA = 40;
    constexpr int NB  = NOUT * 4 / 256;      // uint4 per thread per (hi|lo) B tile
    constexpr int NSEL = LOPASS ? 2 : 1;
    constexpr int ABUF = BM * LDA * 2;           // bytes per A buffer
    constexpr int BBUF = NSEL * NOUT * LDA * 2;  // bytes per B buffer

    __shared__ __half As[2][BM][LDA];
    __shared__ __half Bs[2][NSEL][NOUT][LDA];

    int t = threadIdx.x, lane = t & 31, w = t >> 5;
    int g = lane >> 2, tq = lane & 3;
    int wm = (w / WC) * (MT * 16);
    int wn = (w % WC) * 32;
    int m0 = blockIdx.x * BM;

    unsigned asBase = (unsigned)__cvta_generic_to_shared(&As[0][0][0]);
    unsigned bsBase = (unsigned)__cvta_generic_to_shared(&Bs[0][0][0][0]);

    float acc[MT][NT][4];
#pragma unroll
    for (int i = 0; i < MT; i++)
#pragma unroll
        for (int j = 0; j < NT; j++)
#pragma unroll
            for (int q = 0; q < 4; q++) acc[i][j][q] = 0.f;

    int aRow = lane & 15, aCol = (lane >> 4) << 3;
    int bN = lane & 7, bQ = lane >> 3;
    int bSel = LOPASS ? (bQ >> 1) : 0;
    int bCol = (bQ & 1) << 3;
    int aR0 = t >> 2, aC0 = (t & 3) * 8;
    int bR = t >> 2, bC8 = (t & 3) * 8;      // B staging coords (idx = t, + i*256)

    // prologue: prefetch tile 0 into regs (A and B)
    uint4 pa[2], pb[NB], pl[LOPASS ? NB : 1];
#pragma unroll
    for (int i = 0; i < 2; i++)
        pa[i] = *reinterpret_cast<const uint4*>(&A0[(m0 + aR0 + i * 64) * F + aC0]);
#pragma unroll
    for (int i = 0; i < NB; i++) {
        int r = bR + i * 64;
        pb[i] = *reinterpret_cast<const uint4*>(&BH[r * 384 + bC8]);
        if (LOPASS) pl[i] = *reinterpret_cast<const uint4*>(&BL[r * 384 + bC8]);
    }

#pragma unroll 1
    for (int kti = 0; kti < 12; kti++) {
        int kt = kti * 32;
        int buf = kti & 1;
        // store prefetched tile into this buffer
#pragma unroll
        for (int i = 0; i < 2; i++)
            *reinterpret_cast<uint4*>(&As[buf][aR0 + i * 64][aC0]) = pa[i];
#pragma unroll
        for (int i = 0; i < NB; i++) {
            int r = bR + i * 64;
            *reinterpret_cast<uint4*>(&Bs[buf][0][r][bC8]) = pb[i];
            if (LOPASS) *reinterpret_cast<uint4*>(&Bs[buf][NSEL - 1][r][bC8]) = pl[i];
        }
        // prefetch next tile into regs (LDG latency hides under compute)
        if (kti < 11) {
            int ktn = kt + 32;
            const __half* A = (ktn < 128) ? A0 : ((ktn < 256) ? A1 : A2);
            int kc = ktn & 127;
#pragma unroll
            for (int i = 0; i < 2; i++)
                pa[i] = *reinterpret_cast<const uint4*>(&A[(m0 + aR0 + i * 64) * F + kc + aC0]);
#pragma unroll
            for (int i = 0; i < NB; i++) {
                int r = bR + i * 64;
                pb[i] = *reinterpret_cast<const uint4*>(&BH[r * 384 + ktn + bC8]);
                if (LOPASS) pl[i] = *reinterpret_cast<const uint4*>(&BL[r * 384 + ktn + bC8]);
            }
        }
        __syncthreads();   // buffer `buf` visible; also gates reuse of buf two iters out
#pragma unroll
        for (int ks = 0; ks < 2; ks++) {
            int kb = ks * 16;
            unsigned a[MT][4];
#pragma unroll
            for (int mt = 0; mt < MT; mt++)
                ldsm_x4(a[mt], asBase + buf * ABUF + ((wm + mt * 16 + aRow) * LDA + kb + aCol) * 2);
            if (LOPASS) {
                unsigned bb[NT][4];
#pragma unroll
                for (int nt = 0; nt < NT; nt++)
                    ldsm_x4(bb[nt], bsBase + buf * BBUF + ((bSel * NOUT + wn + nt * 8 + bN) * LDA + kb + bCol) * 2);
#pragma unroll
                for (int mt = 0; mt < MT; mt++)
#pragma unroll
                    for (int nt = 0; nt < NT; nt++) {
                        mma_f16(acc[mt][nt], a[mt], bb[nt]);
                        mma_f16(acc[mt][nt], a[mt], bb[nt] + 2);
                    }
            } else {
                unsigned bb[NT][2];
#pragma unroll
                for (int nt = 0; nt < NT; nt++)
                    ldsm_x2(bb[nt], bsBase + buf * BBUF + (((wn + nt * 8 + (lane & 7)) * LDA + kb + ((lane >> 3) << 3)) * 2));
#pragma unroll
                for (int mt = 0; mt < MT; mt++)
#pragma unroll
                    for (int nt = 0; nt < NT; nt++)
                        mma_f16(acc[mt][nt], a[mt], bb[nt]);
            }
        }
    }

#pragma unroll
    for (int mt = 0; mt < MT; mt++)
#pragma unroll
        for (int nt = 0; nt < NT; nt++) {
            int n = wn + nt * 8 + tq * 2;
            float b0 = __ldg(&bias[n]), b1 = __ldg(&bias[n + 1]);
#pragma unroll
            for (int half = 0; half < 2; half++) {
                int m = m0 + wm + mt * 16 + g + half * 8;
                if (m >= NN) continue;
                float v0 = acc[mt][nt][2 * half]     + b0;
                float v1 = acc[mt][nt][2 * half + 1] + b1;
                if (RES) {
                    float2 rf = __half22float2(*reinterpret_cast<const __half2*>(&res[m * F + n]));
                    v0 += rf.x; v1 += rf.y;
                }
                if (RELU) { v0 = fmaxf(v0, 0.f); v1 = fmaxf(v1, 0.f); }
                if (OUTF32)
                    *reinterpret_cast<float2*>(&out[m * NOUT + n]) = make_float2(v0, v1);
                if (OUTH)
                    outh[m * (NOUT / 2) + n / 2] = __floats2half2_rn(v0, v1);
            }
        }
}

// ------------------------------------------------ launch
extern "C" void kernel_launch(void* const* d_in, const int* in_sizes, int n_in,
                              void* d_out, int out_size) {
    const float* x     = (const float*)d_in[0];
    const int*   ei    = (const int*)d_in[1];
    const float* ew    = (const float*)d_in[2];
    const float* W_in  = (const float*)d_in[3];
    const float* b_in  = (const float*)d_in[4];
    const float* W_h1  = (const float*)d_in[5];
    const float* b_h1  = (const float*)d_in[6];
    const float* W_h2  = (const float*)d_in[7];
    const float* b_h2  = (const float*)d_in[8];
    const float* W_out = (const float*)d_in[9];
    const float* b_out = (const float*)d_in[10];
    float* out = (float*)d_out;

    const int* row = ei;
    const int* col = ei + NE;

    __half* hbuf; cudaGetSymbolAddress((void**)&hbuf, g_hbuf);
    int* cnt;     cudaGetSymbolAddress((void**)&cnt,  g_cnt);
    __half* wh;   cudaGetSymbolAddress((void**)&wh,   g_wh);
    __half* wl;   cudaGetSymbolAddress((void**)&wl,   g_wl);

    const size_t S = (size_t)MPAD * F;
    __half* Xh  = hbuf;
    __half* Hh  = hbuf + S;
    __half* T1h = hbuf + 2 * S;
    __half* T2h = hbuf + 3 * S;
    const int WSZ = 128 * 384;
    __half *WH0 = wh,           *WL0 = wl;
    __half *WH1 = wh + WSZ,     *WL1 = wl + WSZ;
    __half *WH2 = wh + 2 * WSZ, *WL2 = wl + 2 * WSZ;
    __half *WH3 = wh + 3 * WSZ, *WL3 = wl + 3 * WSZ;

    const int spmmGrid = (NN * 16) / 256;   // 6250, exact
    const int gemmGrid = MPAD / 128;        // 782

    k_prep<<<2048, 256>>>(row, (const float4*)x, (__half2*)Xh, NN * F / 4,
                          W_in, W_h1, W_h2, W_out);
    k_scan<<<1, 1024>>>();
    k_scatter<<<1024, 256>>>(row, col, ew);

    // layer 1
    k_spmm<<<spmmGrid, 256>>>((const uint4*)Xh,  (uint4*)T1h);
    k_spmm<<<spmmGrid, 256>>>((const uint4*)T1h, (uint4*)T2h);
    k_gemm<128, true, false, false, true, false><<<gemmGrid, 256>>>(
        Xh, T1h, T2h, WH0, WL0, b_in, nullptr, nullptr, (__half2*)Hh);

    // layer 2 (residual Hh): Hh -> Xh
    k_spmm<<<spmmGrid, 256>>>((const uint4*)Hh,  (uint4*)T1h);
    k_spmm<<<spmmGrid, 256>>>((const uint4*)T1h, (uint4*)T2h);
    k_gemm<128, true, true, false, true, false><<<gemmGrid, 256>>>(
        Hh, T1h, T2h, WH1, WL1, b_h1, Hh, nullptr, (__half2*)Xh);

    // layer 3 (residual Xh): Xh -> Hh
    k_spmm<<<spmmGrid, 256>>>((const uint4*)Xh,  (uint4*)T1h);
    k_spmm<<<spmmGrid, 256>>>((const uint4*)T1h, (uint4*)T2h);
    k_gemm<128, true, true, false, true, false><<<gemmGrid, 256>>>(
        Xh, T1h, T2h, WH2, WL2, b_h2, Xh, nullptr, (__half2*)Hh);

    // output layer: Hh -> out (N x 64, fp32), 2-pass weights for final precision
    k_spmm<<<spmmGrid, 256>>>((const uint4*)Hh,  (uint4*)T1h);
    k_spmm<<<spmmGrid, 256>>>((const uint4*)T1h, (uint4*)T2h);
    k_gemm<64, false, false, true, false, true><<<gemmGrid, 256>>>(
        Hh, T1h, T2h, WH3, WL3, b_out, nullptr, out, nullptr);

    // restore g_cnt=0 invariant for the next call
    cudaMemsetAsync(cnt, 0, NN * sizeof(int));
}